// round 16
// baseline (speedup 1.0000x reference)
#include <cuda_runtime.h>
#include <cuda_bf16.h>
#include <cstdint>

// Problem constants
#define DM     256
#define HW     3136
#define NB     2
#define PTOT   (NB*HW)       // 6272 = 49*128 (fused pixel axis)
#define NH     8
#define HD     32
#define WS     7
#define NW     49

// Scratch (device globals). Fused layout: [c][P] with c = h*32+d, P = b*HW+p.
__device__ float g_q[DM * PTOT];
__device__ float g_k[DM * PTOT];
__device__ float g_v[DM * PTOT];
__device__ float g_a[DM * PTOT];

// Pre-converted tf32 weights in MMA fragment layout.
__device__ uint4 g_wf[4][16384];   // q,k,v,o — 1 MB total

typedef unsigned long long u64;
// ---- packed f32x2 helpers ---------------------------------------------------
__device__ __forceinline__ u64 pack2s(float v) {
    u64 r; asm("mov.b64 %0, {%1, %1};" : "=l"(r) : "f"(v)); return r;
}
__device__ __forceinline__ u64 packpair(float a, float b) {
    u64 r; asm("mov.b64 %0, {%1, %2};" : "=l"(r) : "f"(a), "f"(b)); return r;
}
__device__ __forceinline__ void ffma2(u64& d, u64 a, u64 b) {
    asm("fma.rn.f32x2 %0, %1, %2, %0;" : "+l"(d) : "l"(a), "l"(b));
}
__device__ __forceinline__ float2 unpack2(u64 v) {
    float2 r; asm("mov.b64 {%0, %1}, %2;" : "=f"(r.x), "=f"(r.y) : "l"(v)); return r;
}

// ---- cp.async helpers -------------------------------------------------------
__device__ __forceinline__ uint32_t smem_u32(const void* p) {
    uint32_t a;
    asm("{ .reg .u64 t; cvta.to.shared.u64 t, %1; cvt.u32.u64 %0, t; }" : "=r"(a) : "l"(p));
    return a;
}
__device__ __forceinline__ void cpa4(uint32_t dst, const float* src, bool ok) {
    asm volatile("cp.async.ca.shared.global [%0], [%1], 4, %2;"
        :: "r"(dst), "l"(src), "r"(ok ? 4u : 0u) : "memory");
}
#define CPA_COMMIT() asm volatile("cp.async.commit_group;" ::: "memory")
#define CPA_WAIT2()  asm volatile("cp.async.wait_group 2;" ::: "memory")

// ---- tf32 mma helpers ------------------------------------------------------
__device__ __forceinline__ uint32_t f2tf32(float v) {
    uint32_t r; asm("cvt.rna.tf32.f32 %0, %1;" : "=r"(r) : "f"(v)); return r;
}
__device__ __forceinline__ void mma_tf32(float* d, const uint32_t* a, const uint32_t* b) {
    asm volatile(
        "mma.sync.aligned.m16n8k8.row.col.f32.tf32.tf32.f32 "
        "{%0,%1,%2,%3}, {%4,%5,%6,%7}, {%8,%9}, {%0,%1,%2,%3};"
        : "+f"(d[0]), "+f"(d[1]), "+f"(d[2]), "+f"(d[3])
        : "r"(a[0]), "r"(a[1]), "r"(a[2]), "r"(a[3]), "r"(b[0]), "r"(b[1]));
}

#define BPAD 136

__device__ __forceinline__ void cvt_store4(uint32_t* dst, float4 v) {
    uint4 t;
    t.x = f2tf32(v.x); t.y = f2tf32(v.y); t.z = f2tf32(v.z); t.w = f2tf32(v.w);
    *(uint4*)dst = t;
}

// ---------------------------------------------------------------------------
// Prepass: convert 4 weight matrices to fragment-layout tf32.
// ---------------------------------------------------------------------------
__global__ __launch_bounds__(256) void wfrag_kernel(
    const float* __restrict__ wq, const float* __restrict__ wk,
    const float* __restrict__ wv, const float* __restrict__ wo)
{
    const int gidx = blockIdx.x * 256 + threadIdx.x;
    const int m = gidx >> 14;
    const int rI = gidx & 16383;
    const float* W = (m == 0) ? wq : (m == 1) ? wk : (m == 2) ? wv : wo;

    const int lane = rI & 31;
    const int t    = (rI >> 5) & 1;
    const int kk   = (rI >> 6) & 3;
    const int kc   = (rI >> 8) & 7;
    const int wm   = (rI >> 11) & 3;
    const int oi   = (rI >> 13) & 1;

    const int row = oi * 128 + wm * 32 + t * 16 + (lane >> 2);
    const int col = kc * 32 + kk * 8 + (lane & 3);

    uint4 v;
    v.x = f2tf32(W[(size_t)row * DM + col]);
    v.y = f2tf32(W[(size_t)(row + 8) * DM + col]);
    v.z = f2tf32(W[(size_t)row * DM + col + 4]);
    v.w = f2tf32(W[(size_t)(row + 8) * DM + col + 4]);
    g_wf[m][rI] = v;
}

// ---------------------------------------------------------------------------
// tf32 MMA GEMM body (R15 measured-best).
// ---------------------------------------------------------------------------
struct GemmRegs { float d[2][8][4]; };

template <bool QKV>
__device__ __forceinline__ void gemm_mma_body(
    GemmRegs& R, uint32_t* Bs,
    const uint4* __restrict__ wf,
    const float* __restrict__ x,
    int o0, int p0, int tid)
{
    const int lane = tid & 31, wid = tid >> 5;
    const int gid = lane >> 2, tg = lane & 3;
    const int wm = wid & 3, wn = wid >> 2;
    const int cbase = wn * 64;
    const int oi = o0 >> 7;

    const uint4* __restrict__ afb = wf + ((oi * 4 + wm) * 2048 + lane);

    #pragma unroll
    for (int t = 0; t < 2; t++)
        #pragma unroll
        for (int j = 0; j < 8; j++)
            #pragma unroll
            for (int q = 0; q < 4; q++) R.d[t][j][q] = 0.f;

    const int bk  = tid >> 3;
    const int bpx = (tid & 7) * 16;
    const float* bsrc;
    if (QKV) {
        const int P16 = p0 + bpx;
        const int bt  = (P16 >= HW) ? 1 : 0;
        bsrc = x + (size_t)bt * DM * HW + (size_t)bk * HW + (P16 - bt * HW);
    } else {
        bsrc = g_a + (size_t)bk * PTOT + p0 + bpx;
    }
    const size_t brstride = QKV ? (size_t)HW : (size_t)PTOT;

    float4 bR[4];
    #pragma unroll
    for (int i = 0; i < 4; i++) bR[i] = ((const float4*)bsrc)[i];

    for (int kc = 0; kc < 8; kc++) {
        #pragma unroll
        for (int i = 0; i < 4; i++)
            cvt_store4(&Bs[bk * BPAD + bpx + i * 4], bR[i]);
        __syncthreads();

        if (kc < 7) {
            const float* br = bsrc + (size_t)((kc + 1) * 32) * brstride;
            #pragma unroll
            for (int i = 0; i < 4; i++) bR[i] = ((const float4*)br)[i];
        }

        uint4 aF[8];
        {
            const uint4* af = afb + kc * 256;
            #pragma unroll
            for (int kk = 0; kk < 4; kk++) {
                aF[kk * 2]     = af[kk * 64];
                aF[kk * 2 + 1] = af[kk * 64 + 32];
            }
        }

        #pragma unroll
        for (int kk = 0; kk < 4; kk++) {
            const int kb = kk * 8;
            uint32_t b[8][2];
            #pragma unroll
            for (int j = 0; j < 8; j++) {
                const int col = cbase + j * 8 + gid;
                b[j][0] = Bs[(kb + tg)     * BPAD + col];
                b[j][1] = Bs[(kb + tg + 4) * BPAD + col];
            }
            #pragma unroll
            for (int t = 0; t < 2; t++)
                #pragma unroll
                for (int j = 0; j < 8; j++)
                    mma_tf32(R.d[t][j], (const uint32_t*)&aF[kk * 2 + t], b[j]);
        }
        __syncthreads();
    }
}

// ---------------------------------------------------------------------------
__global__ __launch_bounds__(256, 2) void qkv_mma_kernel(
    const float* __restrict__ x,
    const float* __restrict__ bq, const float* __restrict__ bk,
    const float* __restrict__ bv)
{
    __shared__ __align__(16) uint32_t Bs[32 * BPAD];

    const int m = blockIdx.z;
    const float* __restrict__ bias = (m == 0) ? bq : (m == 1) ? bk : bv;
    float* __restrict__ out        = (m == 0) ? g_q : (m == 1) ? g_k : g_v;

    const int p0 = blockIdx.x * 128;
    const int o0 = blockIdx.y * 128;
    const int tid = threadIdx.x;

    GemmRegs R;
    gemm_mma_body<true>(R, Bs, g_wf[m], x, o0, p0, tid);

    const int lane = tid & 31, wid = tid >> 5;
    const int gid = lane >> 2, tg = lane & 3;
    const int wm = wid & 3, wn = wid >> 2;
    #pragma unroll
    for (int t = 0; t < 2; t++) {
        const int orow = o0 + wm * 32 + t * 16 + gid;
        const float b0 = bias[orow], b1 = bias[orow + 8];
        #pragma unroll
        for (int j = 0; j < 8; j++) {
            const int px = p0 + wn * 64 + j * 8 + 2 * tg;
            *(float2*)(out + (size_t)orow * PTOT + px) =
                make_float2(R.d[t][j][0] + b0, R.d[t][j][1] + b0);
            *(float2*)(out + (size_t)(orow + 8) * PTOT + px) =
                make_float2(R.d[t][j][2] + b1, R.d[t][j][3] + b1);
        }
    }
}

__global__ __launch_bounds__(256, 2) void oproj_mma_kernel(
    const float* __restrict__ bo, float* __restrict__ outp)
{
    __shared__ __align__(16) uint32_t Bs[32 * BPAD];

    const int p0 = blockIdx.x * 128;
    const int o0 = blockIdx.y * 128;
    const int tid = threadIdx.x;

    GemmRegs R;
    gemm_mma_body<false>(R, Bs, g_wf[3], nullptr, o0, p0, tid);

    const int lane = tid & 31, wid = tid >> 5;
    const int gid = lane >> 2, tg = lane & 3;
    const int wm = wid & 3, wn = wid >> 2;
    #pragma unroll
    for (int t = 0; t < 2; t++) {
        const int orow = o0 + wm * 32 + t * 16 + gid;
        const float b0 = bo[orow], b1 = bo[orow + 8];
        #pragma unroll
        for (int j = 0; j < 8; j++) {
            const int P8 = p0 + wn * 64 + j * 8;
            const int bt = (P8 >= HW) ? 1 : 0;
            const int px = P8 - bt * HW + 2 * tg;
            float* d0 = outp + ((size_t)bt * DM + orow) * HW + px;
            float* d1 = outp + ((size_t)bt * DM + orow + 8) * HW + px;
            *(float2*)d0 = make_float2(R.d[t][j][0] + b0, R.d[t][j][1] + b0);
            *(float2*)d1 = make_float2(R.d[t][j][2] + b1, R.d[t][j][3] + b1);
        }
    }
}

// ---------------------------------------------------------------------------
// Windowed attention: 4x56 tiles, 2 px/thread, packed f32x2 scores.
// 4 d-slices per pipeline stage (8 stages/phase), aligned-pair FFMA2,
// scale deferred into softmax. grid (14, 16), block 128.
// ---------------------------------------------------------------------------
#define SROWS 10
#define SLICE4 (SROWS * 64)       // 640
#define PIPE 4
#define DQ   4                    // d-slices per stage

// One slice's score update: 4 aligned u64 pairs + 3 constructed odd pairs.
__device__ __forceinline__ void slice_scores(u64* s01, u64 qj, const float* sl)
{
    #pragma unroll
    for (int dy = 0; dy < WS; dy++) {
        const float* row = sl + dy * 64;
        u64 tu0 = *(const u64*)(row);
        u64 tu1 = *(const u64*)(row + 2);
        u64 tu2 = *(const u64*)(row + 4);
        u64 tu3 = *(const u64*)(row + 6);
        float2 t0 = unpack2(tu0), t1 = unpack2(tu1);
        float2 t2 = unpack2(tu2), t3 = unpack2(tu3);
        ffma2(s01[dy * WS + 0], qj, tu0);
        ffma2(s01[dy * WS + 1], qj, packpair(t0.y, t1.x));
        ffma2(s01[dy * WS + 2], qj, tu1);
        ffma2(s01[dy * WS + 3], qj, packpair(t1.y, t2.x));
        ffma2(s01[dy * WS + 4], qj, tu2);
        ffma2(s01[dy * WS + 5], qj, packpair(t2.y, t3.x));
        ffma2(s01[dy * WS + 6], qj, tu3);
    }
}

__device__ __forceinline__ void slice_out(u64& acc, const u64* s01, const float* sl)
{
    #pragma unroll
    for (int dy = 0; dy < WS; dy++) {
        const float* row = sl + dy * 64;
        u64 tu0 = *(const u64*)(row);
        u64 tu1 = *(const u64*)(row + 2);
        u64 tu2 = *(const u64*)(row + 4);
        u64 tu3 = *(const u64*)(row + 6);
        float2 t0 = unpack2(tu0), t1 = unpack2(tu1);
        float2 t2 = unpack2(tu2), t3 = unpack2(tu3);
        ffma2(acc, s01[dy * WS + 0], tu0);
        ffma2(acc, s01[dy * WS + 1], packpair(t0.y, t1.x));
        ffma2(acc, s01[dy * WS + 2], tu1);
        ffma2(acc, s01[dy * WS + 3], packpair(t1.y, t2.x));
        ffma2(acc, s01[dy * WS + 4], tu2);
        ffma2(acc, s01[dy * WS + 5], packpair(t2.y, t3.x));
        ffma2(acc, s01[dy * WS + 6], tu3);
    }
}

__global__ __launch_bounds__(128) void attn_kernel()
{
    const int z   = blockIdx.y;
    const int b   = z >> 3;
    const int h   = z & 7;
    const int y0  = blockIdx.x * 4;
    const int tid = threadIdx.x;
    const bool act = (tid < 112);
    const int r   = act ? (tid / 28) : 3;
    const int xp  = act ? (tid - (tid / 28) * 28) : 0;
    const int x0  = xp * 2;
    const int p   = (y0 + r) * 56 + x0;

    const size_t base = (size_t)(h * HD) * PTOT + (size_t)b * HW;
    const float* __restrict__ qbase = g_q + base;
    const float* __restrict__ kbase = g_k + base;
    const float* __restrict__ vbase = g_v + base;
    float*       __restrict__ abase = g_a + base;

    __shared__ __align__(16) float sk[PIPE][DQ][SLICE4];   // 40 KB
    const uint32_t skb = smem_u32(sk);

    int  goff[5];
    bool gok[5];
    uint32_t dby[5];
    #pragma unroll
    for (int it = 0; it < 5; it++) {
        int idx = tid + it * 128;
        int row = idx >> 6;
        int col = idx & 63;
        int gy = y0 - 3 + row;
        int gx = col - 3;
        gok[it]  = ((unsigned)gy < 56u) && ((unsigned)gx < 56u);
        goff[it] = gok[it] ? (gy * 56 + gx) : 0;
        dby[it]  = (uint32_t)idx * 4u;
    }

    u64 s01[NW];
    #pragma unroll
    for (int i = 0; i < NW; i++) s01[i] = 0ull;

    // ---- Phase 1: scores (K pipeline, 4 slices/stage) ----
    #pragma unroll
    for (int s = 0; s < PIPE - 1; s++) {
        const uint32_t sb = skb + (uint32_t)s * (DQ * SLICE4 * 4);
        #pragma unroll
        for (int q = 0; q < DQ; q++) {
            const float* gA = kbase + (size_t)(DQ * s + q) * PTOT;
            #pragma unroll
            for (int it = 0; it < 5; it++)
                cpa4(sb + q * (SLICE4 * 4) + dby[it], gA + goff[it], gok[it]);
        }
        CPA_COMMIT();
    }

    for (int i = 0; i < 8; i++) {
        CPA_WAIT2();
        __syncthreads();
        if (i + 3 < 8) {
            const int s = i + 3;
            const uint32_t sb = skb + (uint32_t)(s & 3) * (DQ * SLICE4 * 4);
            #pragma unroll
            for (int q = 0; q < DQ; q++) {
                const float* gA = kbase + (size_t)(DQ * s + q) * PTOT;
                #pragma unroll
                for (int it = 0; it < 5; it++)
                    cpa4(sb + q * (SLICE4 * 4) + dby[it], gA + goff[it], gok[it]);
            }
        }
        CPA_COMMIT();

        #pragma unroll
        for (int q = 0; q < DQ; q++) {
            float2 qv = *(const float2*)(qbase + (size_t)(DQ * i + q) * PTOT + p);
            const u64 qj = packpair(qv.x, qv.y);
            slice_scores(s01, qj, &sk[i & 3][q][r * 64 + x0]);
        }
    }

    // ---- Softmax (scale deferred: softmax over s*scale) ----
    {
        const float scale = 0.17677669529663687f;
        float mx0, mx1;
        {
            float2 t = unpack2(s01[0]);
            mx0 = t.x; mx1 = t.y;
        }
        #pragma unroll
        for (int i = 1; i < NW; i++) {
            float2 t = unpack2(s01[i]);
            mx0 = fmaxf(mx0, t.x); mx1 = fmaxf(mx1, t.y);
        }
        float sum0 = 0.f, sum1 = 0.f;
        float e0[NW], e1[NW];
        #pragma unroll
        for (int i = 0; i < NW; i++) {
            float2 t = unpack2(s01[i]);
            e0[i] = __expf((t.x - mx0) * scale); sum0 += e0[i];
            e1[i] = __expf((t.y - mx1) * scale); sum1 += e1[i];
        }
        const float inv0 = 1.f / sum0;
        const float inv1 = 1.f / sum1;
        #pragma unroll
        for (int i = 0; i < NW; i++)
            s01[i] = packpair(e0[i] * inv0, e1[i] * inv1);
    }

    // ---- Phase 2: output (V pipeline) ----
    asm volatile("cp.async.wait_group 0;" ::: "memory");
    __syncthreads();
    #pragma unroll
    for (int s = 0; s < PIPE - 1; s++) {
        const uint32_t sb = skb + (uint32_t)s * (DQ * SLICE4 * 4);
        #pragma unroll
        for (int q = 0; q < DQ; q++) {
            const float* gA = vbase + (size_t)(DQ * s + q) * PTOT;
            #pragma unroll
            for (int it = 0; it < 5; it++)
                cpa4(sb + q * (SLICE4 * 4) + dby[it], gA + goff[it], gok[it]);
        }
        CPA_COMMIT();
    }

    for (int i = 0; i < 8; i++) {
        CPA_WAIT2();
        __syncthreads();
        if (i + 3 < 8) {
            const int s = i + 3;
            const uint32_t sb = skb + (uint32_t)(s & 3) * (DQ * SLICE4 * 4);
            #pragma unroll
            for (int q = 0; q < DQ; q++) {
                const float* gA = vbase + (size_t)(DQ * s + q) * PTOT;
                #pragma unroll
                for (int it = 0; it < 5; it++)
                    cpa4(sb + q * (SLICE4 * 4) + dby[it], gA + goff[it], gok[it]);
            }
        }
        CPA_COMMIT();

        u64 acc[DQ] = {0ull, 0ull, 0ull, 0ull};
        #pragma unroll
        for (int q = 0; q < DQ; q++)
            slice_out(acc[q], s01, &sk[i & 3][q][r * 64 + x0]);

        if (act) {
            #pragma unroll
            for (int q = 0; q < DQ; q++)
                *(float2*)(abase + (size_t)(DQ * i + q) * PTOT + p) = unpack2(acc[q]);
        }
    }
}

// ---------------------------------------------------------------------------
extern "C" void kernel_launch(void* const* d_in, const int* in_sizes, int n_in,
                              void* d_out, int out_size)
{
    (void)in_sizes; (void)n_in; (void)out_size;
    const float* x  = (const float*)d_in[0];
    const float* wq = (const float*)d_in[1];
    const float* bq = (const float*)d_in[2];
    const float* wk = (const float*)d_in[3];
    const float* bk = (const float*)d_in[4];
    const float* wv = (const float*)d_in[5];
    const float* bv = (const float*)d_in[6];
    const float* wo = (const float*)d_in[7];
    const float* bo = (const float*)d_in[8];
    float* out = (float*)d_out;

    wfrag_kernel<<<256, 256>>>(wq, wk, wv, wo);
    qkv_mma_kernel<<<dim3(PTOT / 128, DM / 128, 3), 256>>>(x, bq, bk, bv);
    attn_kernel<<<dim3(14, NB * NH), 128>>>();
    oproj_mma_kernel<<<dim3(PTOT / 128, DM / 128), 256>>>(bo, out);
}